// round 11
// baseline (speedup 1.0000x reference)
#include <cuda_runtime.h>
#include <math.h>

// DCN collapsed-affine, round 11: R10 chain + split-row k_main.
// k_main: 1024 thr (32 warps), 16 rows/block, EACH ROW SPLIT ACROSS 2 WARPS
// (13 features each, full depth-13 prefetch), grid 256. 8192 warps chip-wide.

#define EPSF 1e-5f

constexpr int Bn   = 4096;
constexpr int Fn   = 26;
constexpr int Vn   = 10000;
constexpr int Dn   = 64;
constexpr int D0   = 1664;   // Fn*Dn
constexpr int NUMB = 13;
constexpr int INW  = 1677;   // D0 + NUMB
constexpr int H1   = 1024;
constexpr int H2   = 512;
constexpr int H3   = 256;

// Scratch (device globals)
__device__ float g_v3p[16][H2];
__device__ float g_v2p[16][H1];
__device__ float g_u[1792];
__device__ float g_r;

__device__ __forceinline__ float warp_sum(float v) {
    #pragma unroll
    for (int o = 16; o; o >>= 1) v += __shfl_xor_sync(0xffffffffu, v, o);
    return v;
}

// ---------------------------------------------------------------------------
__global__ __launch_bounds__(256) void k_v3(
    const float* __restrict__ w3, const float* __restrict__ bn3,
    const float* __restrict__ pred_w, const float* __restrict__ pred_b) {
    int bid = blockIdx.x;
    int ib = bid >> 1, jb = bid & 1;
    int t = threadIdx.x;
    int i0 = ib * 16;
    __shared__ float ts[16];
    if (t < 16) {
        int i = i0 + t;
        float a3 = bn3[i] * rsqrtf(bn3[3 * H3 + i] + EPSF);
        ts[t] = a3 * pred_w[D0 + i];
    }
    int gt = bid * 256 + t;
    if (gt < 1792) g_u[gt] = 0.f;
    if (gt == 0) g_r = pred_b[0];
    __syncthreads();
    int j = jb * 256 + t;
    float acc = 0.f;
    #pragma unroll
    for (int i = 0; i < 16; i++) acc += w3[(i0 + i) * H2 + j] * ts[i];
    g_v3p[ib][j] = acc;
}

// ---------------------------------------------------------------------------
__global__ __launch_bounds__(128) void k_v2(
    const float* __restrict__ w2, const float* __restrict__ bn2,
    const float* __restrict__ b2, const float* __restrict__ bn3,
    const float* __restrict__ b3, const float* __restrict__ pred_w) {
    int bid = blockIdx.x;
    int jb = bid & 7, ib = bid >> 3;
    int t = threadIdx.x;
    int i0 = ib * 32;
    __shared__ float ts[32];
    __shared__ float red[4];
    float rloc = 0.f;

    if (t < 32) {
        int i = i0 + t;
        float v3 = 0.f;
        #pragma unroll
        for (int p = 0; p < 16; p++) v3 += g_v3p[p][i];
        float a2 = bn2[i] * rsqrtf(bn2[3 * H2 + i] + EPSF);
        ts[t] = a2 * v3;
        if (jb == 0)
            rloc += (a2 * b2[i] + bn2[H2 + i] - bn2[2 * H2 + i] * a2) * v3;
    }
    if (bid == 0) {
        #pragma unroll
        for (int i = t; i < H3; i += 128) {
            float a3 = bn3[i] * rsqrtf(bn3[3 * H3 + i] + EPSF);
            rloc += (a3 * b3[i] + bn3[H3 + i] - bn3[2 * H3 + i] * a3) * pred_w[D0 + i];
        }
    }
    __syncthreads();

    int j = jb * 128 + t;
    float acc = 0.f;
    #pragma unroll 8
    for (int i = 0; i < 32; i++) acc += w2[(i0 + i) * H1 + j] * ts[i];
    g_v2p[ib][j] = acc;

    if (jb == 0) {
        rloc = warp_sum(rloc);
        if ((t & 31) == 0) red[t >> 5] = rloc;
        __syncthreads();
        if (t == 0) atomicAdd(&g_r, red[0] + red[1] + red[2] + red[3]);
    }
}

// ---------------------------------------------------------------------------
__global__ __launch_bounds__(256) void k_u(
    const float* __restrict__ w1, const float* __restrict__ bn1,
    const float* __restrict__ b1, const float* __restrict__ bn0) {
    int bid = blockIdx.x;
    int jb = bid % 7, ib = bid / 7;
    int t = threadIdx.x;
    int i0 = ib * 32;
    __shared__ float ts[32];
    __shared__ float red[8];
    float rloc = 0.f;

    if (t < 32) {
        int i = i0 + t;
        float v2 = 0.f;
        #pragma unroll
        for (int p = 0; p < 16; p++) v2 += g_v2p[p][i];
        float a1 = bn1[i] * rsqrtf(bn1[3 * H1 + i] + EPSF);
        ts[t] = a1 * v2;
        if (jb == 0)
            rloc += (a1 * b1[i] + bn1[H1 + i] - bn1[2 * H1 + i] * a1) * v2;
    }
    __syncthreads();

    int j = jb * 256 + t;
    if (j < INW) {
        float acc = 0.f;
        #pragma unroll 8
        for (int i = 0; i < 32; i++)
            acc += w1[(size_t)(i0 + i) * INW + j] * ts[i];
        atomicAdd(&g_u[j], acc);
        float a0 = bn0[j] * rsqrtf(bn0[3 * INW + j] + EPSF);
        float c0 = bn0[INW + j] - bn0[2 * INW + j] * a0;
        rloc += c0 * acc;
    }

    rloc = warp_sum(rloc);
    if ((t & 31) == 0) red[t >> 5] = rloc;
    __syncthreads();
    if (t == 0) {
        float rb = 0.f;
        #pragma unroll
        for (int w = 0; w < 8; w++) rb += red[w];
        atomicAdd(&g_r, rb);
    }
}

// ---------------------------------------------------------------------------
// Main gather kernel: 1024 thr (32 warps), 16 rows/block, 2 warps per row
// (feature halves of 13), grid 256. Full depth-13 prefetch per warp.
__global__ __launch_bounds__(1024, 1) void k_main(
    const float* __restrict__ numb, const int* __restrict__ cat,
    const float* __restrict__ emb,  const float* __restrict__ cross_w,
    const float* __restrict__ cross_b, const float* __restrict__ pred_w,
    const float* __restrict__ bn0, float* __restrict__ out) {

    __shared__ float2 sv0[832], sv1[832], sv2[832], sv3[832], sv4[832];
    __shared__ float  s_qn[16];
    __shared__ float  redm[3][32];
    __shared__ float  s_sc[4];
    __shared__ float  part[16][2][5];

    const int tid   = threadIdx.x;
    const int warp  = tid >> 5;
    const int lane  = tid & 31;
    const int rloc_ = warp & 15;       // row within block
    const int half  = warp >> 4;       // feature half 0/1
    const int f0    = half * 13;
    const int row   = blockIdx.x * 16 + rloc_;

    int mi = (lane < 13) ? cat[row * Fn + f0 + lane] : 0;

    // ---- prologue: staging, q from g_u, Sc sums ----
    float p1 = 0.f, p2 = 0.f, p3 = 0.f;
    {
        const float2* cwp = (const float2*)cross_w;
        const float2* pwp = (const float2*)pred_w;
        if (tid < 832) {
            float2 c0 = cwp[tid];
            float2 c1 = cwp[832 + tid];
            float2 c2 = cwp[1664 + tid];
            float2 pw = pwp[tid];
            sv0[tid] = c0; sv1[tid] = c1; sv2[tid] = c2; sv3[tid] = pw;
            p1 = c1.x + c1.y; p2 = c2.x + c2.y; p3 = pw.x + pw.y;
        }
        float* sv4f = (float*)sv4;
        {
            int j = tid;              // < D0
            float a0 = bn0[j] * rsqrtf(bn0[3 * INW + j] + EPSF);
            sv4f[j] = a0 * g_u[j];
        }
        {
            int j = tid + 1024;
            if (j < INW) {
                float a0 = bn0[j] * rsqrtf(bn0[3 * INW + j] + EPSF);
                float q = a0 * g_u[j];
                if (j < D0) sv4f[j] = q;
                else        s_qn[j - D0] = q;
            }
        }
        if (tid == 0) s_sc[3] = g_r;
    }
    p1 = warp_sum(p1); p2 = warp_sum(p2); p3 = warp_sum(p3);
    if (lane == 0) { redm[0][warp] = p1; redm[1][warp] = p2; redm[2][warp] = p3; }
    __syncthreads();
    if (tid < 32) {
        float a = warp_sum(redm[0][tid]);
        float b = warp_sum(redm[1][tid]);
        float c = warp_sum(redm[2][tid]);
        if (tid == 0) { s_sc[0] = a; s_sc[1] = b; s_sc[2] = c; }
    }
    __syncthreads();

    // ---- gather: 13 features per warp, full prefetch ----
    float acc0 = 0.f, acc1 = 0.f, acc2 = 0.f, acc3 = 0.f, acc4 = 0.f;

    #define EMB_LD(FF) \
        __ldg(reinterpret_cast<const float2*>(emb + (size_t)(f0 + (FF)) * (Vn * Dn)) \
              + (size_t)__shfl_sync(0xffffffffu, mi, (FF)) * 32 + lane)

    float2 e[13];
    #pragma unroll
    for (int ff = 0; ff < 13; ff++) e[ff] = EMB_LD(ff);
    #undef EMB_LD

    #pragma unroll
    for (int ff = 0; ff < 13; ff++) {
        int b = (f0 + ff) * 32 + lane;
        float2 ev = e[ff];
        float2 c;
        c = sv0[b]; acc0 += ev.x * c.x + ev.y * c.y;
        c = sv1[b]; acc1 += ev.x * c.x + ev.y * c.y;
        c = sv2[b]; acc2 += ev.x * c.x + ev.y * c.y;
        c = sv3[b]; acc3 += ev.x * c.x + ev.y * c.y;
        c = sv4[b]; acc4 += ev.x * c.x + ev.y * c.y;
    }

    if (half == 1 && lane < NUMB)
        acc4 += numb[row * NUMB + lane] * s_qn[lane];

    acc0 = warp_sum(acc0);
    acc1 = warp_sum(acc1);
    acc2 = warp_sum(acc2);
    acc3 = warp_sum(acc3);
    acc4 = warp_sum(acc4);

    if (lane == 0) {
        part[rloc_][half][0] = acc0;
        part[rloc_][half][1] = acc1;
        part[rloc_][half][2] = acc2;
        part[rloc_][half][3] = acc3;
        part[rloc_][half][4] = acc4;
    }
    __syncthreads();

    // ---- epilogue: 16 threads, one per row ----
    if (tid < 16) {
        float d0 = part[tid][0][0] + part[tid][1][0];
        float d1 = part[tid][0][1] + part[tid][1][1];
        float d2 = part[tid][0][2] + part[tid][1][2];
        float d3 = part[tid][0][3] + part[tid][1][3];
        float d4 = part[tid][0][4] + part[tid][1][4];

        float cb0 = cross_b[0], cb1 = cross_b[1], cb2 = cross_b[2];
        float Sc1 = s_sc[0], Sc2 = s_sc[1], Sp = s_sc[2], rtot = s_sc[3];

        float al = d0 + 1.f;
        float be = cb0;
        float sd1 = al * d1 + be * Sc1;
        al = (sd1 + 1.f) * al;
        be = (sd1 + 1.f) * be + cb1;
        float sd2 = al * d2 + be * Sc2;
        al = (sd2 + 1.f) * al;
        be = (sd2 + 1.f) * be + cb2;

        float z = al * d3 + be * Sp + d4 + rtot;
        out[blockIdx.x * 16 + tid] = 1.f / (1.f + expf(-z));
    }
}

// ---------------------------------------------------------------------------
extern "C" void kernel_launch(void* const* d_in, const int* in_sizes, int n_in,
                              void* d_out, int out_size) {
    const float* numb    = (const float*)d_in[0];
    const int*   cat     = (const int*)  d_in[1];
    const float* emb     = (const float*)d_in[2];
    const float* bn0     = (const float*)d_in[3];
    const float* w1      = (const float*)d_in[4];
    const float* b1      = (const float*)d_in[5];
    const float* bn1     = (const float*)d_in[6];
    const float* w2      = (const float*)d_in[7];
    const float* b2      = (const float*)d_in[8];
    const float* bn2     = (const float*)d_in[9];
    const float* w3      = (const float*)d_in[10];
    const float* b3      = (const float*)d_in[11];
    const float* bn3     = (const float*)d_in[12];
    const float* cross_w = (const float*)d_in[13];
    const float* cross_b = (const float*)d_in[14];
    const float* pred_w  = (const float*)d_in[15];
    const float* pred_b  = (const float*)d_in[16];
    float* out = (float*)d_out;

    k_v3<<<32, 256>>>(w3, bn3, pred_w, pred_b);
    k_v2<<<128, 128>>>(w2, bn2, b2, bn3, b3, pred_w);
    k_u<<<224, 256>>>(w1, bn1, b1, bn0);
    k_main<<<256, 1024>>>(numb, cat, emb, cross_w, cross_b, pred_w, bn0, out);
}

// round 12
// speedup vs baseline: 1.0992x; 1.0992x over previous
#include <cuda_runtime.h>
#include <math.h>

// DCN collapsed-affine, round 12: exact R7 k_main (best measured, 12.0us)
// + exact R10 chain (best measured, ~2-5us). Pure recombination.

#define EPSF 1e-5f

constexpr int Bn   = 4096;
constexpr int Fn   = 26;
constexpr int Vn   = 10000;
constexpr int Dn   = 64;
constexpr int D0   = 1664;   // Fn*Dn
constexpr int NUMB = 13;
constexpr int INW  = 1677;   // D0 + NUMB
constexpr int H1   = 1024;
constexpr int H2   = 512;
constexpr int H3   = 256;

// Scratch (device globals)
__device__ float g_v3p[16][H2];
__device__ float g_v2p[16][H1];
__device__ float g_u[1792];
__device__ float g_r;

__device__ __forceinline__ float warp_sum(float v) {
    #pragma unroll
    for (int o = 16; o; o >>= 1) v += __shfl_xor_sync(0xffffffffu, v, o);
    return v;
}

// ---------------------------------------------------------------------------
__global__ __launch_bounds__(256) void k_v3(
    const float* __restrict__ w3, const float* __restrict__ bn3,
    const float* __restrict__ pred_w, const float* __restrict__ pred_b) {
    int bid = blockIdx.x;
    int ib = bid >> 1, jb = bid & 1;
    int t = threadIdx.x;
    int i0 = ib * 16;
    __shared__ float ts[16];
    if (t < 16) {
        int i = i0 + t;
        float a3 = bn3[i] * rsqrtf(bn3[3 * H3 + i] + EPSF);
        ts[t] = a3 * pred_w[D0 + i];
    }
    int gt = bid * 256 + t;
    if (gt < 1792) g_u[gt] = 0.f;
    if (gt == 0) g_r = pred_b[0];
    __syncthreads();
    int j = jb * 256 + t;
    float acc = 0.f;
    #pragma unroll
    for (int i = 0; i < 16; i++) acc += w3[(i0 + i) * H2 + j] * ts[i];
    g_v3p[ib][j] = acc;
}

// ---------------------------------------------------------------------------
__global__ __launch_bounds__(128) void k_v2(
    const float* __restrict__ w2, const float* __restrict__ bn2,
    const float* __restrict__ b2, const float* __restrict__ bn3,
    const float* __restrict__ b3, const float* __restrict__ pred_w) {
    int bid = blockIdx.x;
    int jb = bid & 7, ib = bid >> 3;
    int t = threadIdx.x;
    int i0 = ib * 32;
    __shared__ float ts[32];
    __shared__ float red[4];
    float rloc = 0.f;

    if (t < 32) {
        int i = i0 + t;
        float v3 = 0.f;
        #pragma unroll
        for (int p = 0; p < 16; p++) v3 += g_v3p[p][i];
        float a2 = bn2[i] * rsqrtf(bn2[3 * H2 + i] + EPSF);
        ts[t] = a2 * v3;
        if (jb == 0)
            rloc += (a2 * b2[i] + bn2[H2 + i] - bn2[2 * H2 + i] * a2) * v3;
    }
    if (bid == 0) {
        #pragma unroll
        for (int i = t; i < H3; i += 128) {
            float a3 = bn3[i] * rsqrtf(bn3[3 * H3 + i] + EPSF);
            rloc += (a3 * b3[i] + bn3[H3 + i] - bn3[2 * H3 + i] * a3) * pred_w[D0 + i];
        }
    }
    __syncthreads();

    int j = jb * 128 + t;
    float acc = 0.f;
    #pragma unroll 8
    for (int i = 0; i < 32; i++) acc += w2[(i0 + i) * H1 + j] * ts[i];
    g_v2p[ib][j] = acc;

    if (jb == 0) {
        rloc = warp_sum(rloc);
        if ((t & 31) == 0) red[t >> 5] = rloc;
        __syncthreads();
        if (t == 0) atomicAdd(&g_r, red[0] + red[1] + red[2] + red[3]);
    }
}

// ---------------------------------------------------------------------------
__global__ __launch_bounds__(256) void k_u(
    const float* __restrict__ w1, const float* __restrict__ bn1,
    const float* __restrict__ b1, const float* __restrict__ bn0) {
    int bid = blockIdx.x;
    int jb = bid % 7, ib = bid / 7;
    int t = threadIdx.x;
    int i0 = ib * 32;
    __shared__ float ts[32];
    __shared__ float red[8];
    float rloc = 0.f;

    if (t < 32) {
        int i = i0 + t;
        float v2 = 0.f;
        #pragma unroll
        for (int p = 0; p < 16; p++) v2 += g_v2p[p][i];
        float a1 = bn1[i] * rsqrtf(bn1[3 * H1 + i] + EPSF);
        ts[t] = a1 * v2;
        if (jb == 0)
            rloc += (a1 * b1[i] + bn1[H1 + i] - bn1[2 * H1 + i] * a1) * v2;
    }
    __syncthreads();

    int j = jb * 256 + t;
    if (j < INW) {
        float acc = 0.f;
        #pragma unroll 8
        for (int i = 0; i < 32; i++)
            acc += w1[(size_t)(i0 + i) * INW + j] * ts[i];
        atomicAdd(&g_u[j], acc);
        float a0 = bn0[j] * rsqrtf(bn0[3 * INW + j] + EPSF);
        float c0 = bn0[INW + j] - bn0[2 * INW + j] * a0;
        rloc += c0 * acc;
    }

    rloc = warp_sum(rloc);
    if ((t & 31) == 0) red[t >> 5] = rloc;
    __syncthreads();
    if (t == 0) {
        float rb = 0.f;
        #pragma unroll
        for (int w = 0; w < 8; w++) rb += red[w];
        atomicAdd(&g_r, rb);
    }
}

// ---------------------------------------------------------------------------
// Main gather kernel: 512 thr (16 warps, 1 row/warp), grid 256, 2 blocks/SM.
// Depth-13 register prefetch: 13 independent gather loads always in flight.
__global__ __launch_bounds__(512, 2) void k_main(
    const float* __restrict__ numb, const int* __restrict__ cat,
    const float* __restrict__ emb,  const float* __restrict__ cross_w,
    const float* __restrict__ cross_b, const float* __restrict__ pred_w,
    const float* __restrict__ bn0, float* __restrict__ out) {

    __shared__ float2 sv0[832], sv1[832], sv2[832], sv3[832], sv4[832];
    __shared__ float  s_qn[16];
    __shared__ float  redm[3][16];
    __shared__ float  s_sc[4];

    const int tid  = threadIdx.x;
    const int warp = tid >> 5;
    const int lane = tid & 31;
    const int row  = blockIdx.x * 16 + warp;

    int mi = (lane < Fn) ? cat[row * Fn + lane] : 0;

    // ---- prologue: staging, q from g_u, Sc sums ----
    float p1 = 0.f, p2 = 0.f, p3 = 0.f;
    {
        const float2* cwp = (const float2*)cross_w;
        const float2* pwp = (const float2*)pred_w;
        #pragma unroll
        for (int k = tid; k < 832; k += 512) {
            float2 c0 = cwp[k];
            float2 c1 = cwp[832 + k];
            float2 c2 = cwp[1664 + k];
            float2 pw = pwp[k];
            sv0[k] = c0; sv1[k] = c1; sv2[k] = c2; sv3[k] = pw;
            p1 += c1.x + c1.y; p2 += c2.x + c2.y; p3 += pw.x + pw.y;
        }
        float* sv4f = (float*)sv4;
        #pragma unroll
        for (int j = tid; j < INW; j += 512) {
            float a0 = bn0[j] * rsqrtf(bn0[3 * INW + j] + EPSF);
            float q = a0 * g_u[j];
            if (j < D0) sv4f[j] = q;
            else        s_qn[j - D0] = q;
        }
        if (tid == 0) s_sc[3] = g_r;
    }
    p1 = warp_sum(p1); p2 = warp_sum(p2); p3 = warp_sum(p3);
    if (lane == 0) { redm[0][warp] = p1; redm[1][warp] = p2; redm[2][warp] = p3; }
    __syncthreads();
    if (tid < 32) {
        float a = (tid < 16) ? redm[0][tid] : 0.f;
        float b = (tid < 16) ? redm[1][tid] : 0.f;
        float c = (tid < 16) ? redm[2][tid] : 0.f;
        a = warp_sum(a); b = warp_sum(b); c = warp_sum(c);
        if (tid == 0) { s_sc[0] = a; s_sc[1] = b; s_sc[2] = c; }
    }
    __syncthreads();

    // ---- gather: depth-13 register pipeline ----
    float acc0 = 0.f, acc1 = 0.f, acc2 = 0.f, acc3 = 0.f, acc4 = 0.f;
    float2 e[13];

    #define EMB_LD(F) \
        __ldg(reinterpret_cast<const float2*>(emb + (size_t)(F) * (Vn * Dn)) \
              + (size_t)__shfl_sync(0xffffffffu, mi, (F)) * 32 + lane)

    #pragma unroll
    for (int ff = 0; ff < 13; ff++) e[ff] = EMB_LD(ff);

    #pragma unroll
    for (int f = 0; f < Fn; f++) {
        float2 ev = e[f % 13];
        if (f + 13 < Fn) e[f % 13] = EMB_LD(f + 13);
        int b = f * 32 + lane;
        float2 c;
        c = sv0[b]; acc0 += ev.x * c.x + ev.y * c.y;
        c = sv1[b]; acc1 += ev.x * c.x + ev.y * c.y;
        c = sv2[b]; acc2 += ev.x * c.x + ev.y * c.y;
        c = sv3[b]; acc3 += ev.x * c.x + ev.y * c.y;
        c = sv4[b]; acc4 += ev.x * c.x + ev.y * c.y;
    }
    #undef EMB_LD

    if (lane < NUMB) acc4 += numb[row * NUMB + lane] * s_qn[lane];

    acc0 = warp_sum(acc0);
    acc1 = warp_sum(acc1);
    acc2 = warp_sum(acc2);
    acc3 = warp_sum(acc3);
    acc4 = warp_sum(acc4);

    if (lane == 0) {
        float cb0 = cross_b[0], cb1 = cross_b[1], cb2 = cross_b[2];
        float Sc1 = s_sc[0], Sc2 = s_sc[1], Sp = s_sc[2], rtot = s_sc[3];

        float al = acc0 + 1.f;
        float be = cb0;
        float sd1 = al * acc1 + be * Sc1;
        al = (sd1 + 1.f) * al;
        be = (sd1 + 1.f) * be + cb1;
        float sd2 = al * acc2 + be * Sc2;
        al = (sd2 + 1.f) * al;
        be = (sd2 + 1.f) * be + cb2;

        float z = al * acc3 + be * Sp + acc4 + rtot;
        out[row] = 1.f / (1.f + expf(-z));
    }
}

// ---------------------------------------------------------------------------
extern "C" void kernel_launch(void* const* d_in, const int* in_sizes, int n_in,
                              void* d_out, int out_size) {
    const float* numb    = (const float*)d_in[0];
    const int*   cat     = (const int*)  d_in[1];
    const float* emb     = (const float*)d_in[2];
    const float* bn0     = (const float*)d_in[3];
    const float* w1      = (const float*)d_in[4];
    const float* b1      = (const float*)d_in[5];
    const float* bn1     = (const float*)d_in[6];
    const float* w2      = (const float*)d_in[7];
    const float* b2      = (const float*)d_in[8];
    const float* bn2     = (const float*)d_in[9];
    const float* w3      = (const float*)d_in[10];
    const float* b3      = (const float*)d_in[11];
    const float* bn3     = (const float*)d_in[12];
    const float* cross_w = (const float*)d_in[13];
    const float* cross_b = (const float*)d_in[14];
    const float* pred_w  = (const float*)d_in[15];
    const float* pred_b  = (const float*)d_in[16];
    float* out = (float*)d_out;

    k_v3<<<32, 256>>>(w3, bn3, pred_w, pred_b);
    k_v2<<<128, 128>>>(w2, bn2, b2, bn3, b3, pred_w);
    k_u<<<224, 256>>>(w1, bn1, b1, bn0);
    k_main<<<256, 512>>>(numb, cat, emb, cross_w, cross_b, pred_w, bn0, out);
}